// round 9
// baseline (speedup 1.0000x reference)
#include <cuda_runtime.h>
#include <cuda_fp16.h>
#include <cstdint>

#define NB 4
#define NC 128
#define NN 4096
#define NG 8
#define QSCALE 0.08838834764831845f   // 1/sqrt(128)
#define HPAD 136                      // half stride for fp16 smem tiles
#define XPAD 132                      // float stride for x staging
#define ATILE (128 * HPAD)            // halves per 128x128 tile

// ---------------- scratch (device globals) ----------------------------------
__device__ __half g_q[NB][NN][NC];
__device__ __half g_k[NB][NN][NC];
__device__ __half g_v[NB][NN][NC];
__device__ __half g_h2[NB][NN][NC];
__device__ float  g_stats[NB][NG][2];
__device__ float  g_part[NB * NG][4][2];
__device__ __half g_wqkv_h[3 * NC * NC];  // [o][c]
__device__ __half g_wout_h[NC * NC];

// ---------------- PTX helpers ------------------------------------------------
__device__ __forceinline__ uint32_t smem_to_u32(const void* p) {
    uint32_t a;
    asm("{ .reg .u64 t; cvta.to.shared.u64 t, %1; cvt.u32.u64 %0, t; }"
        : "=r"(a) : "l"(p));
    return a;
}
#define CP16(dst, src) \
    asm volatile("cp.async.cg.shared.global [%0], [%1], 16;" \
                 :: "r"(dst), "l"(src) : "memory")
#define CP_COMMIT() asm volatile("cp.async.commit_group;" ::: "memory")
#define CP_WAIT0()  asm volatile("cp.async.wait_group 0;" ::: "memory")
#define CP_WAIT1()  asm volatile("cp.async.wait_group 1;" ::: "memory")

__device__ __forceinline__ void mma_f16(float4& d, uint32_t a0, uint32_t a1,
                                        uint32_t a2, uint32_t a3,
                                        uint32_t b0, uint32_t b1) {
    asm volatile(
        "mma.sync.aligned.m16n8k16.row.col.f32.f16.f16.f32 "
        "{%0,%1,%2,%3},{%4,%5,%6,%7},{%8,%9},{%0,%1,%2,%3};"
        : "+f"(d.x), "+f"(d.y), "+f"(d.z), "+f"(d.w)
        : "r"(a0), "r"(a1), "r"(a2), "r"(a3), "r"(b0), "r"(b1));
}
__device__ __forceinline__ void ldsm4(uint32_t& r0, uint32_t& r1,
                                      uint32_t& r2, uint32_t& r3, uint32_t a) {
    asm volatile("ldmatrix.sync.aligned.m8n8.x4.shared.b16 {%0,%1,%2,%3}, [%4];"
                 : "=r"(r0), "=r"(r1), "=r"(r2), "=r"(r3) : "r"(a));
}
__device__ __forceinline__ void ldsm4t(uint32_t& r0, uint32_t& r1,
                                       uint32_t& r2, uint32_t& r3, uint32_t a) {
    asm volatile("ldmatrix.sync.aligned.m8n8.x4.trans.shared.b16 {%0,%1,%2,%3}, [%4];"
                 : "=r"(r0), "=r"(r1), "=r"(r2), "=r"(r3) : "r"(a));
}

// ---------------- weight fp16 conversion -------------------------------------
__global__ void prep_kernel(const float* __restrict__ w_qkv,
                            const float* __restrict__ w_out) {
    int t = blockIdx.x * blockDim.x + threadIdx.x;
    int nt = gridDim.x * blockDim.x;
    for (int i = t; i < 3 * NC * NC; i += nt) g_wqkv_h[i] = __float2half(w_qkv[i]);
    for (int i = t; i < NC * NC; i += nt)     g_wout_h[i] = __float2half(w_out[i]);
}

// ---------------- GroupNorm statistics (two-stage) ----------------------------
__global__ void stats1_kernel(const float* __restrict__ x) {
    int grp = blockIdx.x >> 2, chunk = blockIdx.x & 3;
    int b = grp >> 3, g = grp & 7;
    const float4* p = (const float4*)(x + ((size_t)(b * NC + g * 16 + chunk * 4)) * NN);
    const int n4 = 4 * NN / 4;   // 4096 float4
    float s = 0.f, ss = 0.f;
    for (int i = threadIdx.x; i < n4; i += 256) {
        float4 v = p[i];
        s  += v.x + v.y + v.z + v.w;
        ss += v.x * v.x + v.y * v.y + v.z * v.z + v.w * v.w;
    }
    __shared__ float rs[8], rss[8];
    for (int off = 16; off; off >>= 1) {
        s  += __shfl_xor_sync(~0u, s, off);
        ss += __shfl_xor_sync(~0u, ss, off);
    }
    if ((threadIdx.x & 31) == 0) { rs[threadIdx.x >> 5] = s; rss[threadIdx.x >> 5] = ss; }
    __syncthreads();
    if (threadIdx.x < 8) {
        s = rs[threadIdx.x]; ss = rss[threadIdx.x];
        for (int off = 4; off; off >>= 1) {
            s  += __shfl_xor_sync(0xff, s, off);
            ss += __shfl_xor_sync(0xff, ss, off);
        }
        if (threadIdx.x == 0) { g_part[grp][chunk][0] = s; g_part[grp][chunk][1] = ss; }
    }
}
__global__ void stats2_kernel() {
    int t = threadIdx.x;
    if (t < NB * NG) {
        float s = 0.f, ss = 0.f;
        for (int c = 0; c < 4; c++) { s += g_part[t][c][0]; ss += g_part[t][c][1]; }
        float mean = s * (1.f / 65536.f);
        float var = ss * (1.f / 65536.f) - mean * mean;
        g_stats[t >> 3][t & 7][0] = mean;
        g_stats[t >> 3][t & 7][1] = rsqrtf(var + 1e-5f);
    }
}

// ---------------- fused GroupNorm + QKV projection (fp16 mma) ------------------
__global__ void __launch_bounds__(256, 1)
nqkv_kernel(const float* __restrict__ x, const float* __restrict__ gn_w,
            const float* __restrict__ gn_b, const float* __restrict__ b_qkv) {
    extern __shared__ __align__(16) char smraw[];
    float*  xs  = (float*)smraw;                       // [128][XPAD] (c x n)
    __half* h_s = (__half*)(smraw + 128 * XPAD * 4);   // [128][HPAD] (n x c)
    __half* w_s = h_s + ATILE;                         // [384][HPAD] (o x c)
    __shared__ float sc[128], sh[128];
    const uint32_t xs_u = smem_to_u32(xs);
    const uint32_t h_su = smem_to_u32(h_s);
    const uint32_t w_su = smem_to_u32(w_s);

    int b = blockIdx.y, nblk = blockIdx.x * 128;
    int tid = threadIdx.x, wid = tid >> 5, lane = tid & 31;
    int g = lane >> 2, tg = lane & 3;
    int i0 = wid * 16;

    if (tid < 128) {
        int gg = tid >> 4;
        float mean = g_stats[b][gg][0], rstd = g_stats[b][gg][1];
        float w = gn_w[tid], bb = gn_b[tid];
        sc[tid] = rstd * w;
        sh[tid] = bb - mean * rstd * w;
    }

    // G0: x tile (c rows, n cols)
    const float* xb = x + (size_t)b * NC * NN;
#pragma unroll
    for (int t = 0; t < 16; t++) {
        int idx = tid + t * 256;
        int r = idx >> 5, c4 = idx & 31;
        CP16(xs_u + (uint32_t)(r * XPAD + c4 * 4) * 4,
             xb + (size_t)r * NN + nblk + c4 * 4);
    }
    CP_COMMIT();
    // G1: all three weight tiles
#pragma unroll
    for (int t = 0; t < 24; t++) {
        int idx = tid + t * 256;
        int r = idx >> 4, u = idx & 15;
        CP16(w_su + (uint32_t)(r * HPAD + u * 8) * 2,
             g_wqkv_h + (size_t)r * NC + u * 8);
    }
    CP_COMMIT();

    CP_WAIT1();
    __syncthreads();
    // build h_s = groupnorm(x) transposed to [n][c] fp16
#pragma unroll
    for (int t = 0; t < 16; t++) {
        int idx = tid + t * 256;
        int c = idx >> 5, n4 = idx & 31;
        float4 v = *(const float4*)(xs + c * XPAD + n4 * 4);
        float s_ = sc[c], h_ = sh[c];
        h_s[(n4 * 4 + 0) * HPAD + c] = __float2half(v.x * s_ + h_);
        h_s[(n4 * 4 + 1) * HPAD + c] = __float2half(v.y * s_ + h_);
        h_s[(n4 * 4 + 2) * HPAD + c] = __float2half(v.z * s_ + h_);
        h_s[(n4 * 4 + 3) * HPAD + c] = __float2half(v.w * s_ + h_);
    }
    CP_WAIT0();
    __syncthreads();

    // A-fragments (h) resident, shared by all three projections
    uint32_t qa[8][4];
#pragma unroll
    for (int kt = 0; kt < 8; kt++)
        ldsm4(qa[kt][0], qa[kt][1], qa[kt][2], qa[kt][3],
              h_su + (uint32_t)((i0 + (lane & 15)) * HPAD + kt * 16 + ((lane >> 4) << 3)) * 2);

    int n0g = nblk + i0 + g;
#pragma unroll
    for (int ot = 0; ot < 3; ot++) {
        float4 D[16];
#pragma unroll
        for (int j = 0; j < 16; j++) D[j] = make_float4(0.f, 0.f, 0.f, 0.f);
#pragma unroll
        for (int kt = 0; kt < 8; kt++) {
#pragma unroll
            for (int nt = 0; nt < 8; nt++) {
                uint32_t r0, r1, r2, r3;
                ldsm4(r0, r1, r2, r3,
                      w_su + (uint32_t)((ot * 128 + nt * 16 + (lane & 15)) * HPAD +
                                        kt * 16 + ((lane >> 4) << 3)) * 2);
                mma_f16(D[2 * nt],     qa[kt][0], qa[kt][1], qa[kt][2], qa[kt][3], r0, r2);
                mma_f16(D[2 * nt + 1], qa[kt][0], qa[kt][1], qa[kt][2], qa[kt][3], r1, r3);
            }
        }
        __half* dst = (ot == 0) ? &g_q[b][0][0] : (ot == 1) ? &g_k[b][0][0] : &g_v[b][0][0];
        float scale = (ot == 0) ? QSCALE : 1.f;
#pragma unroll
        for (int j = 0; j < 16; j++) {
            int o = (j >> 1) * 16 + (j & 1) * 8 + tg * 2;
            float b0 = b_qkv[ot * 128 + o], b1 = b_qkv[ot * 128 + o + 1];
            *(__half2*)(dst + (size_t)n0g * NC + o) =
                __floats2half2_rn((D[j].x + b0) * scale, (D[j].y + b1) * scale);
            *(__half2*)(dst + (size_t)(n0g + 8) * NC + o) =
                __floats2half2_rn((D[j].z + b0) * scale, (D[j].w + b1) * scale);
        }
    }
}

// ---------------- fp16 mma flash attention (double-buffered) -------------------
__global__ void __launch_bounds__(256, 1) attn5_kernel() {
    extern __shared__ __align__(16) char smraw[];
    __half* k_s0 = (__half*)smraw;
    __half* k_s1 = k_s0 + ATILE;
    __half* v_s0 = k_s1 + ATILE;
    __half* v_s1 = v_s0 + ATILE;
    const uint32_t kb0 = smem_to_u32(k_s0), kb1 = smem_to_u32(k_s1);
    const uint32_t vb0 = smem_to_u32(v_s0), vb1 = smem_to_u32(v_s1);

    int tid = threadIdx.x, wid = tid >> 5, lane = tid & 31;
    int g = lane >> 2, tg = lane & 3;
    int b = blockIdx.y, iblk = blockIdx.x * 128;
    int i0 = wid * 16;
    const __half* qg = &g_q[b][0][0];
    const __half* kg = &g_k[b][0][0];
    const __half* vg = &g_v[b][0][0];

    // G0: K(0)+V(0)
#pragma unroll
    for (int t = 0; t < 8; t++) {
        int idx = tid + t * 256;
        int r = idx >> 4, u = idx & 15;
        CP16(kb0 + (uint32_t)(r * HPAD + u * 8) * 2, kg + (size_t)r * NC + u * 8);
    }
#pragma unroll
    for (int t = 0; t < 8; t++) {
        int idx = tid + t * 256;
        int r = idx >> 4, u = idx & 15;
        CP16(vb0 + (uint32_t)(r * HPAD + u * 8) * 2, vg + (size_t)r * NC + u * 8);
    }
    CP_COMMIT();

    // stage Q through k_s1, extract resident A-fragments
#pragma unroll
    for (int t = 0; t < 8; t++) {
        int idx = tid + t * 256;
        int r = idx >> 4, u = idx & 15;
        *(uint4*)(k_s1 + r * HPAD + u * 8) =
            *(const uint4*)(qg + (size_t)(iblk + r) * NC + u * 8);
    }
    __syncthreads();
    uint32_t qa[8][4];
#pragma unroll
    for (int kt = 0; kt < 8; kt++)
        ldsm4(qa[kt][0], qa[kt][1], qa[kt][2], qa[kt][3],
              kb1 + (uint32_t)((i0 + (lane & 15)) * HPAD + kt * 16 + ((lane >> 4) << 3)) * 2);
    __syncthreads();

    // G1: K(1)+V(1)
#pragma unroll
    for (int t = 0; t < 8; t++) {
        int idx = tid + t * 256;
        int r = idx >> 4, u = idx & 15;
        CP16(kb1 + (uint32_t)(r * HPAD + u * 8) * 2, kg + (size_t)(128 + r) * NC + u * 8);
    }
#pragma unroll
    for (int t = 0; t < 8; t++) {
        int idx = tid + t * 256;
        int r = idx >> 4, u = idx & 15;
        CP16(vb1 + (uint32_t)(r * HPAD + u * 8) * 2, vg + (size_t)(128 + r) * NC + u * 8);
    }
    CP_COMMIT();

    float4 O[16];
#pragma unroll
    for (int j = 0; j < 16; j++) O[j] = make_float4(0.f, 0.f, 0.f, 0.f);
    float lp0 = 0.f, lp1 = 0.f;
    int mat = lane >> 3, rr = lane & 7;

    for (int jt = 0; jt < 32; jt++) {
        uint32_t kbp = (jt & 1) ? kb1 : kb0;
        uint32_t vbp = (jt & 1) ? vb1 : vb0;

        CP_WAIT1();          // group jt landed
        __syncthreads();

        // ---- GEMM1: S = Q K^T ----
        float4 S[16];
#pragma unroll
        for (int j = 0; j < 16; j++) S[j] = make_float4(0.f, 0.f, 0.f, 0.f);
#pragma unroll
        for (int kt = 0; kt < 8; kt++) {
#pragma unroll
            for (int nt = 0; nt < 8; nt++) {
                uint32_t r0, r1, r2, r3;
                ldsm4(r0, r1, r2, r3,
                      kbp + (uint32_t)((nt * 16 + (lane & 15)) * HPAD +
                                       kt * 16 + ((lane >> 4) << 3)) * 2);
                mma_f16(S[2 * nt],     qa[kt][0], qa[kt][1], qa[kt][2], qa[kt][3], r0, r2);
                mma_f16(S[2 * nt + 1], qa[kt][0], qa[kt][1], qa[kt][2], qa[kt][3], r1, r3);
            }
        }

        // ---- fused softmax + GEMM2, per 16-j block (MUFU overlaps tensor) ----
#pragma unroll
        for (int kb = 0; kb < 8; kb++) {
            float e0 = __expf(S[2 * kb].x),     e1 = __expf(S[2 * kb].y);
            float e2 = __expf(S[2 * kb].z),     e3 = __expf(S[2 * kb].w);
            float f0 = __expf(S[2 * kb + 1].x), f1 = __expf(S[2 * kb + 1].y);
            float f2 = __expf(S[2 * kb + 1].z), f3 = __expf(S[2 * kb + 1].w);
            lp0 += e0 + e1 + f0 + f1;
            lp1 += e2 + e3 + f2 + f3;
            __half2 p0 = __floats2half2_rn(e0, e1);
            __half2 p1 = __floats2half2_rn(e2, e3);
            __half2 p2 = __floats2half2_rn(f0, f1);
            __half2 p3 = __floats2half2_rn(f2, f3);
            uint32_t ph0 = *(uint32_t*)&p0, ph1 = *(uint32_t*)&p1;
            uint32_t ph2 = *(uint32_t*)&p2, ph3 = *(uint32_t*)&p3;
#pragma unroll
            for (int nt2 = 0; nt2 < 8; nt2++) {
                uint32_t addr = vbp +
                    (uint32_t)((16 * kb + (mat & 1) * 8 + rr) * HPAD +
                               16 * nt2 + (mat >> 1) * 8) * 2;
                uint32_t r0, r1, r2, r3;
                ldsm4t(r0, r1, r2, r3, addr);
                mma_f16(O[2 * nt2],     ph0, ph1, ph2, ph3, r0, r1);
                mma_f16(O[2 * nt2 + 1], ph0, ph1, ph2, ph3, r2, r3);
            }
        }
        __syncthreads();     // all warps done with buffers p before refill

        // prefetch K(jt+2), V(jt+2) into the just-freed buffers
        if (jt < 30) {
            const __half* kn = kg + (size_t)(jt + 2) * 128 * NC;
            const __half* vn = vg + (size_t)(jt + 2) * 128 * NC;
#pragma unroll
            for (int t = 0; t < 8; t++) {
                int idx = tid + t * 256;
                int r = idx >> 4, u = idx & 15;
                CP16(kbp + (uint32_t)(r * HPAD + u * 8) * 2, kn + (size_t)r * NC + u * 8);
            }
#pragma unroll
            for (int t = 0; t < 8; t++) {
                int idx = tid + t * 256;
                int r = idx >> 4, u = idx & 15;
                CP16(vbp + (uint32_t)(r * HPAD + u * 8) * 2, vn + (size_t)r * NC + u * 8);
            }
        }
        CP_COMMIT();         // empty groups for jt>=30 keep FIFO numbering
    }

    // ---- row-sum reduce over tg quad, scale, store h2 fp16 [N][C] ----
    lp0 += __shfl_xor_sync(~0u, lp0, 1);
    lp0 += __shfl_xor_sync(~0u, lp0, 2);
    lp1 += __shfl_xor_sync(~0u, lp1, 1);
    lp1 += __shfl_xor_sync(~0u, lp1, 2);
    float inv0 = 1.f / lp0, inv1 = 1.f / lp1;

    __half* h2 = &g_h2[b][0][0];
    int row0 = iblk + i0 + g;
#pragma unroll
    for (int nt = 0; nt < 16; nt++) {
        int c = nt * 8 + tg * 2;
        *(__half2*)(h2 + (size_t)row0 * NC + c) =
            __floats2half2_rn(O[nt].x * inv0, O[nt].y * inv0);
        *(__half2*)(h2 + (size_t)(row0 + 8) * NC + c) =
            __floats2half2_rn(O[nt].z * inv1, O[nt].w * inv1);
    }
}

// ---------------- output projection (fp16 mma) + bias + residual ---------------
__global__ void __launch_bounds__(256, 1)
out_mma(const float* __restrict__ x, const float* __restrict__ b_out,
        float* __restrict__ out) {
    extern __shared__ __align__(16) char smraw[];
    __half* w_s  = (__half*)smraw;            // [128][HPAD] (o x c)
    __half* h2_s = w_s + ATILE;               // [128][HPAD] (n x c)
    const uint32_t w_su = smem_to_u32(w_s), h2_su = smem_to_u32(h2_s);

    int nblk = blockIdx.x * 128, b = blockIdx.y;
    int tid = threadIdx.x, wid = tid >> 5, lane = tid & 31;
    int g = lane >> 2, tg = lane & 3;
    int i0 = wid * 16;

#pragma unroll
    for (int t = 0; t < 8; t++) {
        int idx = tid + t * 256;
        int r = idx >> 4, u = idx & 15;
        CP16(w_su + (uint32_t)(r * HPAD + u * 8) * 2, g_wout_h + (size_t)r * NC + u * 8);
        CP16(h2_su + (uint32_t)(r * HPAD + u * 8) * 2, &g_h2[b][nblk + r][u * 8]);
    }
    CP_COMMIT();
    CP_WAIT0();
    __syncthreads();

    float4 D[16];
#pragma unroll
    for (int j = 0; j < 16; j++) D[j] = make_float4(0.f, 0.f, 0.f, 0.f);

#pragma unroll
    for (int kt = 0; kt < 8; kt++) {
        uint32_t a0, a1, a2, a3;
        ldsm4(a0, a1, a2, a3,
              w_su + (uint32_t)((i0 + (lane & 15)) * HPAD + kt * 16 + ((lane >> 4) << 3)) * 2);
#pragma unroll
        for (int nt = 0; nt < 8; nt++) {
            uint32_t r0, r1, r2, r3;
            ldsm4(r0, r1, r2, r3,
                  h2_su + (uint32_t)((nt * 16 + (lane & 15)) * HPAD + kt * 16 + ((lane >> 4) << 3)) * 2);
            mma_f16(D[2 * nt],     a0, a1, a2, a3, r0, r2);
            mma_f16(D[2 * nt + 1], a0, a1, a2, a3, r1, r3);
        }
    }

    int o0 = i0 + g;
    float bo0 = b_out[o0], bo1 = b_out[o0 + 8];
    const float* xr0 = x + ((size_t)(b * NC + o0)) * NN + nblk;
    const float* xr1 = x + ((size_t)(b * NC + o0 + 8)) * NN + nblk;
    float* or0 = out + ((size_t)(b * NC + o0)) * NN + nblk;
    float* or1 = out + ((size_t)(b * NC + o0 + 8)) * NN + nblk;
#pragma unroll
    for (int j = 0; j < 16; j++) {
        int n = (j >> 1) * 16 + (j & 1) * 8 + tg * 2;
        float2 x0 = *(const float2*)(xr0 + n);
        float2 x1 = *(const float2*)(xr1 + n);
        *(float2*)(or0 + n) = make_float2(D[j].x + bo0 + x0.x, D[j].y + bo0 + x0.y);
        *(float2*)(or1 + n) = make_float2(D[j].z + bo1 + x1.x, D[j].w + bo1 + x1.y);
    }
}

// ---------------- launch -----------------------------------------------------
extern "C" void kernel_launch(void* const* d_in, const int* in_sizes, int n_in,
                              void* d_out, int out_size) {
    const float* x     = (const float*)d_in[0];
    const float* gn_w  = (const float*)d_in[1];
    const float* gn_b  = (const float*)d_in[2];
    const float* w_qkv = (const float*)d_in[3];
    const float* b_qkv = (const float*)d_in[4];
    const float* w_out = (const float*)d_in[5];
    const float* b_out = (const float*)d_in[6];
    float* out = (float*)d_out;

    const int TILE = ATILE * 2;                            // 34816 B
    const int SMEM_NQKV = 128 * XPAD * 4 + TILE + 3 * TILE; // 206848
    const int SMEM_ATT  = 4 * TILE;                         // 139264
    const int SMEM_OUT  = 2 * TILE;                         // 69632
    cudaFuncSetAttribute(nqkv_kernel, cudaFuncAttributeMaxDynamicSharedMemorySize, SMEM_NQKV);
    cudaFuncSetAttribute(attn5_kernel, cudaFuncAttributeMaxDynamicSharedMemorySize, SMEM_ATT);
    cudaFuncSetAttribute(out_mma, cudaFuncAttributeMaxDynamicSharedMemorySize, SMEM_OUT);

    prep_kernel<<<64, 256>>>(w_qkv, w_out);
    stats1_kernel<<<128, 256>>>(x);
    stats2_kernel<<<1, 32>>>();
    nqkv_kernel<<<dim3(32, 4), 256, SMEM_NQKV>>>(x, gn_w, gn_b, b_qkv);
    attn5_kernel<<<dim3(32, 4), 256, SMEM_ATT>>>();
    out_mma<<<dim3(32, 4), 256, SMEM_OUT>>>(x, b_out, out);
}